// round 13
// baseline (speedup 1.0000x reference)
#include <cuda_runtime.h>

// g[b,0,i,j] = cos(phi_i + phi_j) with phi = arccos(c)
//            = c_i*c_j - s_i*s_j,  s = sqrt(1 - c^2)
// c = clamp((2x - mx - mn)/(mx - mn), -1+eps, 1-eps) per batch row.
//
// Single kernel, zero barriers, zero smem. Warp-redundant min/max via
// shuffles; lane l precomputes one row's (ci,si); store loop broadcasts
// them via __shfl_sync. Stores use 256-bit st.global.cs.v8.f32 (sm_100+):
// each thread owns 8 consecutive columns and writes 8 rows.
// Champion grain: 32-row chunks, 8192 CTAs of 256 threads, grid (CHUNKS, B).

#define N 512
#define B 512
#define THREADS 256
#define CHUNKS 16                      // row-chunks per batch
#define ROWS_PER_CHUNK (N / CHUNKS)    // 32

__device__ __forceinline__ void stg256_cs(float* p,
                                          const float4& a, const float4& bb) {
    asm volatile(
        "st.global.cs.v8.f32 [%0], {%1,%2,%3,%4,%5,%6,%7,%8};"
        :: "l"(p),
           "f"(a.x), "f"(a.y), "f"(a.z), "f"(a.w),
           "f"(bb.x), "f"(bb.y), "f"(bb.z), "f"(bb.w)
        : "memory");
}

__global__ __launch_bounds__(THREADS)
void gram_kernel(const float* __restrict__ x, float* __restrict__ out) {
    const int chunk = blockIdx.x;
    const int b = blockIdx.y;
    const int tid = threadIdx.x;
    const int lane = tid & 31;

    const float* __restrict__ xb = x + (size_t)b * N;
    const float4* __restrict__ xb4 = (const float4*)xb;

    // Warp-redundant min/max over all 512 floats: 4 lane-strided LDG.128.
    const float4 a0 = __ldg(&xb4[lane]);
    const float4 a1 = __ldg(&xb4[lane + 32]);
    const float4 a2 = __ldg(&xb4[lane + 64]);
    const float4 a3 = __ldg(&xb4[lane + 96]);

    float mn = fminf(fminf(fminf(a0.x, a0.y), fminf(a0.z, a0.w)),
                     fminf(fminf(a1.x, a1.y), fminf(a1.z, a1.w)));
    mn = fminf(mn, fminf(fminf(fminf(a2.x, a2.y), fminf(a2.z, a2.w)),
                         fminf(fminf(a3.x, a3.y), fminf(a3.z, a3.w))));
    float mx = fmaxf(fmaxf(fmaxf(a0.x, a0.y), fmaxf(a0.z, a0.w)),
                     fmaxf(fmaxf(a1.x, a1.y), fmaxf(a1.z, a1.w)));
    mx = fmaxf(mx, fmaxf(fmaxf(fmaxf(a2.x, a2.y), fmaxf(a2.z, a2.w)),
                         fmaxf(fmaxf(a3.x, a3.y), fmaxf(a3.z, a3.w))));
    #pragma unroll
    for (int o = 16; o > 0; o >>= 1) {
        mn = fminf(mn, __shfl_xor_sync(0xFFFFFFFFu, mn, o));
        mx = fmaxf(mx, __shfl_xor_sync(0xFFFFFFFFu, mx, o));
    }

    const float inv = 1.0f / (mx - mn);
    const float shift = mx + mn;
    const float EPS = 1e-6f;

    // This thread's 8 columns: col8 = tid & 63 (8-float group), two float4s.
    const int col8 = tid & 63;
    const int q    = tid >> 6;           // row quarter 0..3 (uniform per warp-pair)
    const float4 xc0 = __ldg(&xb4[2 * col8]);
    const float4 xc1 = __ldg(&xb4[2 * col8 + 1]);

    float4 cj0, sj0, cj1, sj1;
    cj0.x = fminf(fmaxf(fmaf(2.0f, xc0.x, -shift) * inv, -1.0f + EPS), 1.0f - EPS);
    cj0.y = fminf(fmaxf(fmaf(2.0f, xc0.y, -shift) * inv, -1.0f + EPS), 1.0f - EPS);
    cj0.z = fminf(fmaxf(fmaf(2.0f, xc0.z, -shift) * inv, -1.0f + EPS), 1.0f - EPS);
    cj0.w = fminf(fmaxf(fmaf(2.0f, xc0.w, -shift) * inv, -1.0f + EPS), 1.0f - EPS);
    cj1.x = fminf(fmaxf(fmaf(2.0f, xc1.x, -shift) * inv, -1.0f + EPS), 1.0f - EPS);
    cj1.y = fminf(fmaxf(fmaf(2.0f, xc1.y, -shift) * inv, -1.0f + EPS), 1.0f - EPS);
    cj1.z = fminf(fmaxf(fmaf(2.0f, xc1.z, -shift) * inv, -1.0f + EPS), 1.0f - EPS);
    cj1.w = fminf(fmaxf(fmaf(2.0f, xc1.w, -shift) * inv, -1.0f + EPS), 1.0f - EPS);
    sj0.x = sqrtf(fmaxf(fmaf(-cj0.x, cj0.x, 1.0f), 0.0f));
    sj0.y = sqrtf(fmaxf(fmaf(-cj0.y, cj0.y, 1.0f), 0.0f));
    sj0.z = sqrtf(fmaxf(fmaf(-cj0.z, cj0.z, 1.0f), 0.0f));
    sj0.w = sqrtf(fmaxf(fmaf(-cj0.w, cj0.w, 1.0f), 0.0f));
    sj1.x = sqrtf(fmaxf(fmaf(-cj1.x, cj1.x, 1.0f), 0.0f));
    sj1.y = sqrtf(fmaxf(fmaf(-cj1.y, cj1.y, 1.0f), 0.0f));
    sj1.z = sqrtf(fmaxf(fmaf(-cj1.z, cj1.z, 1.0f), 0.0f));
    sj1.w = sqrtf(fmaxf(fmaf(-cj1.w, cj1.w, 1.0f), 0.0f));

    // Per-lane row precompute: lane l owns row (q + 4*(l&7)) of this chunk.
    const int row0 = chunk * ROWS_PER_CHUNK;
    const float xr = __ldg(&xb[row0 + q + 4 * (lane & 7)]);
    float cr = fminf(fmaxf(fmaf(2.0f, xr, -shift) * inv, -1.0f + EPS), 1.0f - EPS);
    float sr = sqrtf(fmaxf(fmaf(-cr, cr, 1.0f), 0.0f));

    float* __restrict__ outp =
        out + (size_t)b * N * N + (size_t)row0 * N + col8 * 8;

    // 8 rows per thread; row (ci,si) broadcast from lane k via shuffle.
    #pragma unroll
    for (int k = 0; k < 8; k++) {
        const float ci = __shfl_sync(0xFFFFFFFFu, cr, k);
        const float si = __shfl_sync(0xFFFFFFFFu, sr, k);
        const int r = q + 4 * k;
        float4 v0, v1;
        v0.x = fmaf(ci, cj0.x, -si * sj0.x);
        v0.y = fmaf(ci, cj0.y, -si * sj0.y);
        v0.z = fmaf(ci, cj0.z, -si * sj0.z);
        v0.w = fmaf(ci, cj0.w, -si * sj0.w);
        v1.x = fmaf(ci, cj1.x, -si * sj1.x);
        v1.y = fmaf(ci, cj1.y, -si * sj1.y);
        v1.z = fmaf(ci, cj1.z, -si * sj1.z);
        v1.w = fmaf(ci, cj1.w, -si * sj1.w);
        stg256_cs(outp + (size_t)r * N, v0, v1);
    }
}

extern "C" void kernel_launch(void* const* d_in, const int* in_sizes, int n_in,
                              void* d_out, int out_size) {
    const float* x = (const float*)d_in[0];
    float* out = (float*)d_out;
    dim3 grid(CHUNKS, B);
    gram_kernel<<<grid, THREADS>>>(x, out);
}

// round 14
// speedup vs baseline: 1.4544x; 1.4544x over previous
#include <cuda_runtime.h>

// g[b,0,i,j] = cos(phi_i + phi_j) with phi = arccos(c)
//            = c_i*c_j - s_i*s_j,  s = sqrt(1 - c^2)
// c = clamp((2x - mx - mn)/(mx - mn), -1+eps, 1-eps) per batch row.
//
// Single kernel, zero barriers, zero smem. Warp-redundant min/max via
// shuffles; lane l precomputes one row's (ci,si); store loop broadcasts
// them via __shfl_sync: body = 2 SHFL + 8 FMA + STG.128 (.cs).
// Champion grain: 32-row chunks, 8192 CTAs of 256 threads.
// Grid = (CHUNKS, B) so consecutive CTAs share a batch row (input locality).
// (Round-12 champion, restored after the v8.f32 store experiment regressed.)

#define N 512
#define B 512
#define THREADS 256
#define CHUNKS 16                      // row-chunks per batch
#define ROWS_PER_CHUNK (N / CHUNKS)    // 32

__global__ __launch_bounds__(THREADS)
void gram_kernel(const float* __restrict__ x, float* __restrict__ out) {
    const int chunk = blockIdx.x;
    const int b = blockIdx.y;
    const int tid = threadIdx.x;
    const int lane = tid & 31;

    const float* __restrict__ xb = x + (size_t)b * N;
    const float4* __restrict__ xb4 = (const float4*)xb;

    // Warp-redundant min/max over all 512 floats: 4 lane-strided LDG.128.
    const float4 a0 = __ldg(&xb4[lane]);
    const float4 a1 = __ldg(&xb4[lane + 32]);
    const float4 a2 = __ldg(&xb4[lane + 64]);
    const float4 a3 = __ldg(&xb4[lane + 96]);

    float mn = fminf(fminf(fminf(a0.x, a0.y), fminf(a0.z, a0.w)),
                     fminf(fminf(a1.x, a1.y), fminf(a1.z, a1.w)));
    mn = fminf(mn, fminf(fminf(fminf(a2.x, a2.y), fminf(a2.z, a2.w)),
                         fminf(fminf(a3.x, a3.y), fminf(a3.z, a3.w))));
    float mx = fmaxf(fmaxf(fmaxf(a0.x, a0.y), fmaxf(a0.z, a0.w)),
                     fmaxf(fmaxf(a1.x, a1.y), fmaxf(a1.z, a1.w)));
    mx = fmaxf(mx, fmaxf(fmaxf(fmaxf(a2.x, a2.y), fmaxf(a2.z, a2.w)),
                         fmaxf(fmaxf(a3.x, a3.y), fmaxf(a3.z, a3.w))));
    #pragma unroll
    for (int o = 16; o > 0; o >>= 1) {
        mn = fminf(mn, __shfl_xor_sync(0xFFFFFFFFu, mn, o));
        mx = fmaxf(mx, __shfl_xor_sync(0xFFFFFFFFu, mx, o));
    }

    const float inv = 1.0f / (mx - mn);
    const float shift = mx + mn;
    const float EPS = 1e-6f;

    // This thread's 4 columns (L1-hot re-read)
    const int col  = tid & 127;          // float4 column group 0..127
    const int half = tid >> 7;           // row parity 0/1 (uniform per warp)
    const float4 xc = __ldg(&xb4[col]);

    float4 cj, sj;
    cj.x = fminf(fmaxf(fmaf(2.0f, xc.x, -shift) * inv, -1.0f + EPS), 1.0f - EPS);
    cj.y = fminf(fmaxf(fmaf(2.0f, xc.y, -shift) * inv, -1.0f + EPS), 1.0f - EPS);
    cj.z = fminf(fmaxf(fmaf(2.0f, xc.z, -shift) * inv, -1.0f + EPS), 1.0f - EPS);
    cj.w = fminf(fmaxf(fmaf(2.0f, xc.w, -shift) * inv, -1.0f + EPS), 1.0f - EPS);
    sj.x = sqrtf(fmaxf(fmaf(-cj.x, cj.x, 1.0f), 0.0f));
    sj.y = sqrtf(fmaxf(fmaf(-cj.y, cj.y, 1.0f), 0.0f));
    sj.z = sqrtf(fmaxf(fmaf(-cj.z, cj.z, 1.0f), 0.0f));
    sj.w = sqrtf(fmaxf(fmaf(-cj.w, cj.w, 1.0f), 0.0f));

    // Per-lane row precompute: lane l owns row (half + 2*(l&15)) of this chunk.
    const int row0 = chunk * ROWS_PER_CHUNK;
    const float xr = __ldg(&xb[row0 + half + 2 * (lane & 15)]);
    float cr = fminf(fmaxf(fmaf(2.0f, xr, -shift) * inv, -1.0f + EPS), 1.0f - EPS);
    float sr = sqrtf(fmaxf(fmaf(-cr, cr, 1.0f), 0.0f));

    float4* __restrict__ out4 =
        (float4*)(out + (size_t)b * N * N + (size_t)row0 * N);

    // 16 rows per thread, processed as 8 interleaved pairs to overlap the
    // SHFL -> FMA -> STG chains of two rows.
    #pragma unroll
    for (int k = 0; k < 16; k += 2) {
        const float ci0 = __shfl_sync(0xFFFFFFFFu, cr, k);
        const float si0 = __shfl_sync(0xFFFFFFFFu, sr, k);
        const float ci1 = __shfl_sync(0xFFFFFFFFu, cr, k + 1);
        const float si1 = __shfl_sync(0xFFFFFFFFu, sr, k + 1);
        const int r0 = half + 2 * k;
        const int r1 = half + 2 * (k + 1);
        float4 v0, v1;
        v0.x = fmaf(ci0, cj.x, -si0 * sj.x);
        v1.x = fmaf(ci1, cj.x, -si1 * sj.x);
        v0.y = fmaf(ci0, cj.y, -si0 * sj.y);
        v1.y = fmaf(ci1, cj.y, -si1 * sj.y);
        v0.z = fmaf(ci0, cj.z, -si0 * sj.z);
        v1.z = fmaf(ci1, cj.z, -si1 * sj.z);
        v0.w = fmaf(ci0, cj.w, -si0 * sj.w);
        v1.w = fmaf(ci1, cj.w, -si1 * sj.w);
        __stcs(&out4[r0 * 128 + col], v0);
        __stcs(&out4[r1 * 128 + col], v1);
    }
}

extern "C" void kernel_launch(void* const* d_in, const int* in_sizes, int n_in,
                              void* d_out, int out_size) {
    const float* x = (const float*)d_in[0];
    float* out = (float*)d_out;
    dim3 grid(CHUNKS, B);
    gram_kernel<<<grid, THREADS>>>(x, out);
}

// round 17
// speedup vs baseline: 1.4593x; 1.0034x over previous
#include <cuda_runtime.h>

// g[b,0,i,j] = cos(phi_i + phi_j) with phi = arccos(c)
//            = c_i*c_j - s_i*s_j,  s = sqrt(1 - c^2)
// c = clamp((2x - mx - mn)/(mx - mn), -1+eps, 1-eps) per batch row.
//
// Single kernel, zero barriers, zero smem. Warp-redundant min/max via
// shuffles; lane l precomputes one row's (ci,si); store loop broadcasts
// them via __shfl_sync: body = 2 SHFL + 8 FMA + STG.128 (.cs).
// Champion grain: 32-row chunks, 8192 CTAs of 256 threads, grid (CHUNKS, B).
// Column values are selected from the reduction's registers (no re-read):
// for warp w, col = (32w + lane) & 127  ==>  xc == a[(w & 3)].

#define N 512
#define B 512
#define THREADS 256
#define CHUNKS 16                      // row-chunks per batch
#define ROWS_PER_CHUNK (N / CHUNKS)    // 32

__global__ __launch_bounds__(THREADS)
void gram_kernel(const float* __restrict__ x, float* __restrict__ out) {
    const int chunk = blockIdx.x;
    const int b = blockIdx.y;
    const int tid = threadIdx.x;
    const int lane = tid & 31;
    const int warp = tid >> 5;

    const float* __restrict__ xb = x + (size_t)b * N;
    const float4* __restrict__ xb4 = (const float4*)xb;

    // Warp-redundant min/max over all 512 floats: 4 lane-strided LDG.128.
    const float4 a0 = __ldg(&xb4[lane]);
    const float4 a1 = __ldg(&xb4[lane + 32]);
    const float4 a2 = __ldg(&xb4[lane + 64]);
    const float4 a3 = __ldg(&xb4[lane + 96]);

    float mn = fminf(fminf(fminf(a0.x, a0.y), fminf(a0.z, a0.w)),
                     fminf(fminf(a1.x, a1.y), fminf(a1.z, a1.w)));
    mn = fminf(mn, fminf(fminf(fminf(a2.x, a2.y), fminf(a2.z, a2.w)),
                         fminf(fminf(a3.x, a3.y), fminf(a3.z, a3.w))));
    float mx = fmaxf(fmaxf(fmaxf(a0.x, a0.y), fmaxf(a0.z, a0.w)),
                     fmaxf(fmaxf(a1.x, a1.y), fmaxf(a1.z, a1.w)));
    mx = fmaxf(mx, fmaxf(fmaxf(fmaxf(a2.x, a2.y), fmaxf(a2.z, a2.w)),
                         fmaxf(fmaxf(a3.x, a3.y), fmaxf(a3.z, a3.w))));
    #pragma unroll
    for (int o = 16; o > 0; o >>= 1) {
        mn = fminf(mn, __shfl_xor_sync(0xFFFFFFFFu, mn, o));
        mx = fmaxf(mx, __shfl_xor_sync(0xFFFFFFFFu, mx, o));
    }

    const float inv = 1.0f / (mx - mn);
    const float shift = mx + mn;
    const float EPS = 1e-6f;

    // This thread's 4 columns: col = (32*warp + lane) & 127; the raw values
    // are already in registers from the reduction (warp-uniform select).
    const int col  = tid & 127;          // float4 column group 0..127
    const int half = tid >> 7;           // row parity 0/1 (uniform per warp)
    const int sel  = warp & 3;           // warp-uniform
    float4 xc;
    if      (sel == 0) xc = a0;
    else if (sel == 1) xc = a1;
    else if (sel == 2) xc = a2;
    else               xc = a3;

    float4 cj, sj;
    cj.x = fminf(fmaxf(fmaf(2.0f, xc.x, -shift) * inv, -1.0f + EPS), 1.0f - EPS);
    cj.y = fminf(fmaxf(fmaf(2.0f, xc.y, -shift) * inv, -1.0f + EPS), 1.0f - EPS);
    cj.z = fminf(fmaxf(fmaf(2.0f, xc.z, -shift) * inv, -1.0f + EPS), 1.0f - EPS);
    cj.w = fminf(fmaxf(fmaf(2.0f, xc.w, -shift) * inv, -1.0f + EPS), 1.0f - EPS);
    sj.x = sqrtf(fmaxf(fmaf(-cj.x, cj.x, 1.0f), 0.0f));
    sj.y = sqrtf(fmaxf(fmaf(-cj.y, cj.y, 1.0f), 0.0f));
    sj.z = sqrtf(fmaxf(fmaf(-cj.z, cj.z, 1.0f), 0.0f));
    sj.w = sqrtf(fmaxf(fmaf(-cj.w, cj.w, 1.0f), 0.0f));

    // Per-lane row precompute: lane l owns row (half + 2*(l&15)) of this chunk.
    const int row0 = chunk * ROWS_PER_CHUNK;
    const float xr = __ldg(&xb[row0 + half + 2 * (lane & 15)]);
    float cr = fminf(fmaxf(fmaf(2.0f, xr, -shift) * inv, -1.0f + EPS), 1.0f - EPS);
    float sr = sqrtf(fmaxf(fmaf(-cr, cr, 1.0f), 0.0f));

    float4* __restrict__ out4 =
        (float4*)(out + (size_t)b * N * N + (size_t)row0 * N);

    // 16 rows per thread, processed as 8 interleaved pairs to overlap the
    // SHFL -> FMA -> STG chains of two rows.
    #pragma unroll
    for (int k = 0; k < 16; k += 2) {
        const float ci0 = __shfl_sync(0xFFFFFFFFu, cr, k);
        const float si0 = __shfl_sync(0xFFFFFFFFu, sr, k);
        const float ci1 = __shfl_sync(0xFFFFFFFFu, cr, k + 1);
        const float si1 = __shfl_sync(0xFFFFFFFFu, sr, k + 1);
        const int r0 = half + 2 * k;
        const int r1 = half + 2 * (k + 1);
        float4 v0, v1;
        v0.x = fmaf(ci0, cj.x, -si0 * sj.x);
        v1.x = fmaf(ci1, cj.x, -si1 * sj.x);
        v0.y = fmaf(ci0, cj.y, -si0 * sj.y);
        v1.y = fmaf(ci1, cj.y, -si1 * sj.y);
        v0.z = fmaf(ci0, cj.z, -si0 * sj.z);
        v1.z = fmaf(ci1, cj.z, -si1 * sj.z);
        v0.w = fmaf(ci0, cj.w, -si0 * sj.w);
        v1.w = fmaf(ci1, cj.w, -si1 * sj.w);
        __stcs(&out4[r0 * 128 + col], v0);
        __stcs(&out4[r1 * 128 + col], v1);
    }
}

extern "C" void kernel_launch(void* const* d_in, const int* in_sizes, int n_in,
                              void* d_out, int out_size) {
    const float* x = (const float*)d_in[0];
    float* out = (float*)d_out;
    dim3 grid(CHUNKS, B);
    gram_kernel<<<grid, THREADS>>>(x, out);
}